// round 16
// baseline (speedup 1.0000x reference)
#include <cuda_runtime.h>
#include <cuda_fp16.h>
#include <math.h>

#define Bq 4
#define Nq 4096
#define Hq 8
#define Dq 64
#define Mq 64
#define BH  (Bq*Hq)       // 32
#define P2  72            // smem row pitch in halves
#define ONESH2 0x3C003C00u
#define KVW (Dq*Mq/2)     // 2048 half2 per bh tile
#define NSEG 64           // 64-row pass1 tiles per bh
#define T1 (NSEG*BH)      // 2048 pass1 tiles
#define T2 (64*BH)        // 2048 pass2 tiles
#define NBLK 1184         // 148*8 blocks

// Scratch + sync state (fully reset by last block each launch; graph-replay safe)
__device__ __half2 g_KVp[NSEG*BH*KVW];
__device__ float   g_Ksp[NSEG*BH*Dq];
__device__ __half2 g_KVh[BH*KVW];
__device__ float   g_Ksum[BH*Dq];
__device__ unsigned g_w1 = 0, g_w2 = 0, g_done = 0;
__device__ unsigned g_cnt[BH];   // zero-init
__device__ unsigned g_flag[BH];  // zero-init

__device__ __forceinline__ float fmap(float x) {
    return x > 0.0f ? x + 1.0f : __expf(x);   // elu(x)+1
}
__device__ __forceinline__ unsigned pack_h2(float lo, float hi) {
    __half2 h = __floats2half2_rn(lo, hi);
    return *reinterpret_cast<unsigned*>(&h);
}
__device__ __forceinline__ void mma_fp16(float4& d,
                                         unsigned a0, unsigned a1, unsigned a2, unsigned a3,
                                         unsigned b0, unsigned b1) {
    asm volatile(
        "mma.sync.aligned.m16n8k16.row.col.f32.f16.f16.f32 "
        "{%0,%1,%2,%3}, {%4,%5,%6,%7}, {%8,%9}, {%0,%1,%2,%3};"
        : "+f"(d.x), "+f"(d.y), "+f"(d.z), "+f"(d.w)
        : "r"(a0), "r"(a1), "r"(a2), "r"(a3), "r"(b0), "r"(b1));
}
__device__ __forceinline__ void ldm_x4t(unsigned& r0, unsigned& r1, unsigned& r2, unsigned& r3,
                                        unsigned addr) {
    asm volatile("ldmatrix.sync.aligned.m8n8.x4.trans.shared.b16 {%0,%1,%2,%3}, [%4];"
        : "=r"(r0), "=r"(r1), "=r"(r2), "=r"(r3) : "r"(addr));
}
__device__ __forceinline__ void ldm_x4(unsigned& r0, unsigned& r1, unsigned& r2, unsigned& r3,
                                       unsigned addr) {
    asm volatile("ldmatrix.sync.aligned.m8n8.x4.shared.b16 {%0,%1,%2,%3}, [%4];"
        : "=r"(r0), "=r"(r1), "=r"(r2), "=r"(r3) : "r"(addr));
}
__device__ __forceinline__ void ldm_x2t(unsigned& r0, unsigned& r1, unsigned addr) {
    asm volatile("ldmatrix.sync.aligned.m8n8.x2.trans.shared.b16 {%0,%1}, [%2];"
        : "=r"(r0), "=r"(r1) : "r"(addr));
}

// ============ fused kernel: pass1 queue -> per-bh reduce -> pass2 queue ============
__global__ void __launch_bounds__(256, 4) fused_kernel(const float* __restrict__ Kp,
                                                       const float* __restrict__ Vp,
                                                       const float* __restrict__ Qp,
                                                       float* __restrict__ Op) {
    __shared__ __align__(16) __half Asm[64][P2];   // K' tile / Q' tile
    __shared__ __align__(16) __half Bsm[64][P2];   // V tile  / KV tile
    __shared__ float Kss[64];
    __shared__ unsigned s_t;

    const int tid = threadIdx.x;
    const int w = tid >> 5, lane = tid & 31;
    const int gid = lane >> 2, tig = lane & 3;
    const int strip = w & 3;
    const int jt0 = (w >> 2) * 4;
    const int g = lane >> 3, r = lane & 7;
    const int arow1 = ((g >> 1) ? 8 : 0) + r;   // pass1 A (trans, x4)
    const int acol1 = (g & 1) ? 8 : 0;
    const int arow2 = ((g & 1) ? 8 : 0) + r;    // pass2 A (non-trans, x4)
    const int acol2 = (g >> 1) ? 8 : 0;
    const int brow  = ((g & 1) ? 8 : 0) + r;    // B (trans, x2)
    const unsigned Abase = (unsigned)__cvta_generic_to_shared(&Asm[0][0]);
    const unsigned Bbase = (unsigned)__cvta_generic_to_shared(&Bsm[0][0]);
    const int nrow = tid >> 4, c4 = tid & 15;

    // ================= phase 1: pass1 work queue =================
    for (;;) {
        __syncthreads();
        if (tid == 0) s_t = atomicAdd(&g_w1, 1u);
        __syncthreads();
        const unsigned t = s_t;
        if (t >= T1) break;
        const int bh = t >> 6, seg = t & 63;
        const int b = bh >> 3, h = bh & 7;
        const int n0 = seg * 64;

        const float* kp = Kp + ((size_t)(b * Nq + n0) * Hq + h) * Dq;
        const float* vp = Vp + ((size_t)(b * Nq + n0) * Hq + h) * Mq;

        // stage (coalesced, fmap + fp16 convert)
        #pragma unroll
        for (int i = 0; i < 4; i++) {
            const int n = i * 16 + nrow;
            const float4 k4 = *(const float4*)(kp + (size_t)n * 512 + c4 * 4);
            const float4 v4 = *(const float4*)(vp + (size_t)n * 512 + c4 * 4);
            uint2 ku, vu;
            ku.x = pack_h2(fmap(k4.x), fmap(k4.y));
            ku.y = pack_h2(fmap(k4.z), fmap(k4.w));
            *(uint2*)&Asm[n][c4 * 4] = ku;
            vu.x = pack_h2(v4.x, v4.y);
            vu.y = pack_h2(v4.z, v4.w);
            *(uint2*)&Bsm[n][c4 * 4] = vu;
        }
        __syncthreads();

        float4 acc[4];
        #pragma unroll
        for (int j = 0; j < 4; j++) acc[j] = make_float4(0.f, 0.f, 0.f, 0.f);
        float4 accK = make_float4(0.f, 0.f, 0.f, 0.f);

        const int d0 = 16 * strip;
        #pragma unroll
        for (int ks = 0; ks < 4; ks++) {
            const int k0 = ks * 16;
            unsigned a0, a1, a2, a3;
            const unsigned aaddr = Abase +
                ((unsigned)((k0 + arow1) * P2 + d0 + acol1)) * 2u;
            ldm_x4t(a0, a1, a2, a3, aaddr);
            if (w < 4)   // Ksum = K'^T @ ones
                mma_fp16(accK, a0, a1, a2, a3, ONESH2, ONESH2);
            #pragma unroll
            for (int j = 0; j < 4; j++) {
                const int m0 = 8 * (jt0 + j);
                unsigned b0, b1;
                const unsigned baddr = Bbase +
                    ((unsigned)((k0 + brow) * P2 + m0)) * 2u;
                ldm_x2t(b0, b1, baddr);
                mma_fp16(acc[j], a0, a1, a2, a3, b0, b1);
            }
        }

        // epilogue: fp16 partials (block exclusively owns [seg][bh])
        __half2* kv = g_KVp + ((size_t)seg * BH + bh) * KVW;
        const int d = d0 + gid;
        #pragma unroll
        for (int j = 0; j < 4; j++) {
            const int m = 8 * (jt0 + j) + 2 * tig;
            kv[(d * Mq + m) >> 1]       = __floats2half2_rn(acc[j].x, acc[j].y);
            kv[((d + 8) * Mq + m) >> 1] = __floats2half2_rn(acc[j].z, acc[j].w);
        }
        if (w < 4 && tig == 0) {
            float* kss = g_Ksp + ((size_t)seg * BH + bh) * Dq;
            kss[d0 + gid]     = accK.x;
            kss[d0 + gid + 8] = accK.z;
        }

        // completion protocol (threadfence-reduction pattern)
        __threadfence();
        __syncthreads();
        if (tid == 0) s_t = atomicAdd(&g_cnt[bh], 1u);
        __syncthreads();
        if (s_t == NSEG - 1) {
            // this block saw the last partial land -> reduce bh
            __threadfence();   // acquire: partials of all segs now visible
            #pragma unroll
            for (int it = 0; it < 2; it++) {
                const int pos4 = it * 256 + tid;   // uint4 index (0..511)
                float s[8];
                #pragma unroll
                for (int q = 0; q < 8; q++) s[q] = 0.0f;
                for (int sg = 0; sg < NSEG; sg++) {
                    const uint4 v = *(const uint4*)(g_KVp +
                        ((size_t)sg * BH + bh) * KVW + pos4 * 4);
                    const unsigned uu[4] = {v.x, v.y, v.z, v.w};
                    #pragma unroll
                    for (int q = 0; q < 4; q++) {
                        const float2 f = __half22float2(*(const __half2*)&uu[q]);
                        s[2 * q] += f.x; s[2 * q + 1] += f.y;
                    }
                }
                uint4 o;
                o.x = pack_h2(s[0], s[1]); o.y = pack_h2(s[2], s[3]);
                o.z = pack_h2(s[4], s[5]); o.w = pack_h2(s[6], s[7]);
                *(uint4*)(g_KVh + (size_t)bh * KVW + pos4 * 4) = o;
            }
            if (tid < 64) {
                float s = 0.0f;
                for (int sg = 0; sg < NSEG; sg++)
                    s += g_Ksp[((size_t)sg * BH + bh) * Dq + tid];
                g_Ksum[bh * Dq + tid] = s;
            }
            __threadfence();
            __syncthreads();
            if (tid == 0) atomicExch(&g_flag[bh], 1u);
        }
    }

    // ================= phase 2: pass2 work queue =================
    for (;;) {
        __syncthreads();
        if (tid == 0) s_t = atomicAdd(&g_w2, 1u);
        __syncthreads();
        const unsigned t = s_t;
        if (t >= T2) break;
        const int bh = t >> 6, nt = t & 63;
        const int b = bh >> 3, h = bh & 7;
        const int n0 = nt * 64;

        // stage Q first (useful DRAM work before any waiting)
        const float* qp = Qp + ((size_t)(b * Nq + n0) * Hq + h) * Dq;
        #pragma unroll
        for (int it = 0; it < 4; it++) {
            const int rr = it * 16 + nrow;
            const float4 q = *(const float4*)(qp + (size_t)rr * 512 + c4 * 4);
            uint2 qu;
            qu.x = pack_h2(fmap(q.x), fmap(q.y));
            qu.y = pack_h2(fmap(q.z), fmap(q.w));
            *(uint2*)&Asm[rr][c4 * 4] = qu;
        }

        // wait for this bh's KV to be reduced
        if (tid == 0) {
            while (atomicAdd(&g_flag[bh], 0u) == 0u) __nanosleep(200);
        }
        __syncthreads();
        __threadfence();   // acquire: KVh/Ksum of bh now visible

        // stage KV (raw fp16 uint4 copy) + Ksum
        const uint4* kvsrc = (const uint4*)(g_KVh + (size_t)bh * KVW);
        #pragma unroll
        for (int it = 0; it < 2; it++) {
            const int job = it * 256 + tid;          // 0..511
            const int rr = job >> 3, cc = job & 7;
            *(uint4*)&Bsm[rr][cc * 8] = kvsrc[job];
        }
        if (tid < 64) Kss[tid] = g_Ksum[bh * Dq + tid];
        __syncthreads();

        float4 acc[4];
        #pragma unroll
        for (int j = 0; j < 4; j++) acc[j] = make_float4(0.f, 0.f, 0.f, 0.f);
        float4 accZ = make_float4(0.f, 0.f, 0.f, 0.f);

        const int nr0 = 16 * strip;
        #pragma unroll
        for (int ks = 0; ks < 4; ks++) {
            const int k0 = ks * 16;
            unsigned a0, a1, a2, a3;
            const unsigned aaddr = Abase +
                ((unsigned)((nr0 + arow2) * P2 + k0 + acol2)) * 2u;
            ldm_x4(a0, a1, a2, a3, aaddr);
            const unsigned zb0 = pack_h2(Kss[k0 + 2 * tig],     Kss[k0 + 2 * tig + 1]);
            const unsigned zb1 = pack_h2(Kss[k0 + 2 * tig + 8], Kss[k0 + 2 * tig + 9]);
            mma_fp16(accZ, a0, a1, a2, a3, zb0, zb1);
            #pragma unroll
            for (int j = 0; j < 4; j++) {
                const int m0 = 8 * (jt0 + j);
                unsigned b0, b1;
                const unsigned baddr = Bbase +
                    ((unsigned)((k0 + brow) * P2 + m0)) * 2u;
                ldm_x2t(b0, b1, baddr);
                mma_fp16(acc[j], a0, a1, a2, a3, b0, b1);
            }
        }

        const float z0 = 1.0f / (accZ.x + 1e-6f);
        const float z1 = 1.0f / (accZ.z + 1e-6f);
        const int row = nr0 + gid;
        float* op0 = Op + ((size_t)(b * Nq + n0 + row) * Hq + h) * Mq;
        float* op1 = op0 + (size_t)8 * Hq * Mq;
        #pragma unroll
        for (int j = 0; j < 4; j++) {
            const int m = 8 * (jt0 + j) + 2 * tig;
            *(float2*)(op0 + m) = make_float2(acc[j].x * z0, acc[j].y * z0);
            *(float2*)(op1 + m) = make_float2(acc[j].z * z1, acc[j].w * z1);
        }
    }

    // ================= exit: last block resets all sync state =================
    __syncthreads();
    if (tid == 0) {
        if (atomicAdd(&g_done, 1u) == NBLK - 1) {
            g_w1 = 0; g_w2 = 0; g_done = 0;
            for (int i = 0; i < BH; i++) { g_cnt[i] = 0; g_flag[i] = 0; }
        }
    }
}

extern "C" void kernel_launch(void* const* d_in, const int* in_sizes, int n_in,
                              void* d_out, int out_size) {
    const float* Q = (const float*)d_in[0];
    const float* K = (const float*)d_in[1];
    const float* V = (const float*)d_in[2];
    float* out = (float*)d_out;

    fused_kernel<<<NBLK, 256>>>(K, V, Q, out);
}

// round 17
// speedup vs baseline: 1.0853x; 1.0853x over previous
#include <cuda_runtime.h>
#include <cuda_fp16.h>
#include <math.h>

#define Bq 4
#define Nq 4096
#define Hq 8
#define Dq 64
#define Mq 64
#define SEG 64          // 64-row pass1 tiles
#define BH  (Bq*Hq)
#define P2  72          // smem row pitch in halves (144B: 16B-aligned, ldmatrix conflict-free)
#define ONESH2 0x3C003C00u   // half2(1.0, 1.0)

// Accumulators: zero at module load; re-zeroed by pass2's last block per bh
// after all 64 pass2 blocks of that bh have staged the tile -> every
// kernel_launch entry (incl. each graph replay) sees zeros. No zero kernel.
__device__ float    g_KV[BH*Dq*Mq];
__device__ float    g_Ksum[BH*Dq];
__device__ unsigned g_cnt[BH];

__device__ __forceinline__ float fmap(float x) {
    return x > 0.0f ? x + 1.0f : __expf(x);   // elu(x)+1
}
__device__ __forceinline__ unsigned pack_h2(float lo, float hi) {
    __half2 h = __floats2half2_rn(lo, hi);
    return *reinterpret_cast<unsigned*>(&h);
}
__device__ __forceinline__ void mma_fp16(float4& d,
                                         unsigned a0, unsigned a1, unsigned a2, unsigned a3,
                                         unsigned b0, unsigned b1) {
    asm volatile(
        "mma.sync.aligned.m16n8k16.row.col.f32.f16.f16.f32 "
        "{%0,%1,%2,%3}, {%4,%5,%6,%7}, {%8,%9}, {%0,%1,%2,%3};"
        : "+f"(d.x), "+f"(d.y), "+f"(d.z), "+f"(d.w)
        : "r"(a0), "r"(a1), "r"(a2), "r"(a3), "r"(b0), "r"(b1));
}
__device__ __forceinline__ void ldm_x4t(unsigned& r0, unsigned& r1, unsigned& r2, unsigned& r3,
                                        unsigned addr) {
    asm volatile("ldmatrix.sync.aligned.m8n8.x4.trans.shared.b16 {%0,%1,%2,%3}, [%4];"
        : "=r"(r0), "=r"(r1), "=r"(r2), "=r"(r3) : "r"(addr));
}
__device__ __forceinline__ void ldm_x4(unsigned& r0, unsigned& r1, unsigned& r2, unsigned& r3,
                                       unsigned addr) {
    asm volatile("ldmatrix.sync.aligned.m8n8.x4.shared.b16 {%0,%1,%2,%3}, [%4];"
        : "=r"(r0), "=r"(r1), "=r"(r2), "=r"(r3) : "r"(addr));
}
__device__ __forceinline__ void ldm_x2t(unsigned& r0, unsigned& r1, unsigned addr) {
    asm volatile("ldmatrix.sync.aligned.m8n8.x2.trans.shared.b16 {%0,%1}, [%2];"
        : "=r"(r0), "=r"(r1) : "r"(addr));
}

// ============ pass1: g_KV[bh] += fmap(K)^T V over this tile's 64 rows ============
// grid (SEG, H, B) = 2048 blocks, 256 thr (8 warps), min 5 blocks/SM.
// Single 64-row chunk, single sync (R15's proven fastest pass1 shape).
// Warp w: d-strip = w&3 (16 d), m j-tiles 4*(w>>2)..+3 (32 m).
// Ksum folded into MMA with B = ones (warps 0-3). fp32 atomic accumulation.
__global__ void __launch_bounds__(256, 5) pass1_kernel(const float* __restrict__ Kp,
                                                       const float* __restrict__ Vp) {
    __shared__ __align__(16) __half Ksm[64][P2];
    __shared__ __align__(16) __half Vsm[64][P2];

    const int b = blockIdx.z, h = blockIdx.y, seg = blockIdx.x;
    const int bh = b * Hq + h;
    const int tid = threadIdx.x;
    const int w = tid >> 5, lane = tid & 31;
    const int gid = lane >> 2, tig = lane & 3;
    const int strip = w & 3;          // d-strip (16 d-rows)
    const int jt0 = (w >> 2) * 4;     // first m j-tile (of 4)
    const int n0 = seg * 64;

    const int g = lane >> 3, r = lane & 7;
    const int arow_off = ((g >> 1) ? 8 : 0) + r;   // A (trans, x4)
    const int acol_off = (g & 1) ? 8 : 0;
    const int brow_off = ((g & 1) ? 8 : 0) + r;    // B (trans, x2)

    const float* kp = Kp + ((size_t)(b * Nq + n0) * Hq + h) * Dq;
    const float* vp = Vp + ((size_t)(b * Nq + n0) * Hq + h) * Mq;
    const int nrow = tid >> 4, c4 = tid & 15;

    // staging: LDG -> fmap/convert -> STS (single chunk)
    #pragma unroll
    for (int i = 0; i < 4; i++) {
        const int n = i * 16 + nrow;
        const float4 k4 = *(const float4*)(kp + (size_t)n * 512 + c4 * 4);
        const float4 v4 = *(const float4*)(vp + (size_t)n * 512 + c4 * 4);
        uint2 ku, vu;
        ku.x = pack_h2(fmap(k4.x), fmap(k4.y));
        ku.y = pack_h2(fmap(k4.z), fmap(k4.w));
        *(uint2*)&Ksm[n][c4 * 4] = ku;
        vu.x = pack_h2(v4.x, v4.y);
        vu.y = pack_h2(v4.z, v4.w);
        *(uint2*)&Vsm[n][c4 * 4] = vu;
    }
    __syncthreads();

    float4 acc[4];
    #pragma unroll
    for (int j = 0; j < 4; j++) acc[j] = make_float4(0.f, 0.f, 0.f, 0.f);
    float4 accK = make_float4(0.f, 0.f, 0.f, 0.f);

    const unsigned Kbase = (unsigned)__cvta_generic_to_shared(&Ksm[0][0]);
    const unsigned Vbase = (unsigned)__cvta_generic_to_shared(&Vsm[0][0]);
    const int d0 = 16 * strip;
    #pragma unroll
    for (int ks = 0; ks < 4; ks++) {
        const int k0 = ks * 16;
        unsigned a0, a1, a2, a3;
        const unsigned aaddr = Kbase +
            ((unsigned)((k0 + arow_off) * P2 + d0 + acol_off)) * 2u;
        ldm_x4t(a0, a1, a2, a3, aaddr);
        if (w < 4)   // Ksum = K'^T @ ones
            mma_fp16(accK, a0, a1, a2, a3, ONESH2, ONESH2);
        #pragma unroll
        for (int j = 0; j < 4; j++) {
            const int m0 = 8 * (jt0 + j);
            unsigned b0, b1;
            const unsigned baddr = Vbase +
                ((unsigned)((k0 + brow_off) * P2 + m0)) * 2u;
            ldm_x2t(b0, b1, baddr);
            mma_fp16(acc[j], a0, a1, a2, a3, b0, b1);
        }
    }

    // epilogue: fire-and-forget fp32 atomic accumulation (proven R12 path)
    float* kv = g_KV + (size_t)bh * Dq * Mq;
    const int d = d0 + gid;
    #pragma unroll
    for (int j = 0; j < 4; j++) {
        const int m = 8 * (jt0 + j) + 2 * tig;
        atomicAdd(&kv[d * Mq + m],           acc[j].x);
        atomicAdd(&kv[d * Mq + m + 1],       acc[j].y);
        atomicAdd(&kv[(d + 8) * Mq + m],     acc[j].z);
        atomicAdd(&kv[(d + 8) * Mq + m + 1], acc[j].w);
    }
    if (w < 4 && tig == 0) {
        atomicAdd(&g_Ksum[bh * Dq + d0 + gid],     accK.x);
        atomicAdd(&g_Ksum[bh * Dq + d0 + gid + 8], accK.z);
    }
}

// ============ pass2: out = Z * fmap(Q) @ KV ; last block per bh re-zeroes state ============
// grid (64, H, B) = 2048 blocks, 256 thr (8 warps), min 4 blocks/SM. 64 n-rows/block.
// Warp w: n-strip = w&3 (16 rows), m j-tiles 4*(w>>2)..+3.
// Z folded into MMA with B = Ksum fragments.
__global__ void __launch_bounds__(256, 4) pass2_kernel(const float* __restrict__ Qp,
                                                       float* __restrict__ Op) {
    __shared__ __align__(16) __half Qsm[64][P2];    // [n][d]
    __shared__ __align__(16) __half KVsm[64][P2];   // [d][m]
    __shared__ float Kss[64];
    __shared__ unsigned s_last;

    const int b = blockIdx.z, h = blockIdx.y;
    const int bh = b * Hq + h;
    const int n0 = blockIdx.x * 64;
    const int tid = threadIdx.x;
    const int w = tid >> 5, lane = tid & 31;
    const int gid = lane >> 2, tig = lane & 3;
    const int strip = w & 3;
    const int jt0 = (w >> 2) * 4;

    const unsigned Qbase  = (unsigned)__cvta_generic_to_shared(&Qsm[0][0]);
    const unsigned KVbase = (unsigned)__cvta_generic_to_shared(&KVsm[0][0]);
    const int g = lane >> 3, r = lane & 7;
    const int arow_off = ((g & 1) ? 8 : 0) + r;    // A (non-trans, x4)
    const int acol_off = (g >> 1) ? 8 : 0;
    const int brow_off = ((g & 1) ? 8 : 0) + r;    // B (trans, x2)

    const float* kvg = g_KV + (size_t)bh * Dq * Mq;
    const float* qp  = Qp + ((size_t)(b * Nq + n0) * Hq + h) * Dq;
    const int nrow = tid >> 4, c4 = tid & 15;

    // staging: KV (fp32 -> fp16) + Q (fmap + convert) + Ksum
    #pragma unroll
    for (int it = 0; it < 4; it++) {
        const int rr = it * 16 + nrow;
        const float4 t = *(const float4*)(kvg + (size_t)rr * Mq + c4 * 4);
        uint2 tu;
        tu.x = pack_h2(t.x, t.y);
        tu.y = pack_h2(t.z, t.w);
        *(uint2*)&KVsm[rr][c4 * 4] = tu;

        const float4 q = *(const float4*)(qp + (size_t)rr * 512 + c4 * 4);
        uint2 qu;
        qu.x = pack_h2(fmap(q.x), fmap(q.y));
        qu.y = pack_h2(fmap(q.z), fmap(q.w));
        *(uint2*)&Qsm[rr][c4 * 4] = qu;
    }
    if (tid < 64) Kss[tid] = g_Ksum[bh * Dq + tid];
    __syncthreads();   // all staging reads of g_KV/g_Ksum complete for this block

    // last-block-per-bh protocol: 64th staged block re-zeroes bh's accumulators
    // (safe: counter==64 implies all 64 blocks' global reads are drained)
    if (tid == 0) s_last = (atomicAdd(&g_cnt[bh], 1u) == 63u) ? 1u : 0u;
    __syncthreads();
    if (s_last) {
        float4 z4 = make_float4(0.f, 0.f, 0.f, 0.f);
        float4* kvz = (float4*)(g_KV + (size_t)bh * Dq * Mq);
        #pragma unroll
        for (int i = 0; i < 4; i++) kvz[i * 256 + tid] = z4;
        if (tid < 64) g_Ksum[bh * Dq + tid] = 0.0f;
        if (tid == 0) g_cnt[bh] = 0;
    }

    float4 acc[4];
    #pragma unroll
    for (int j = 0; j < 4; j++) acc[j] = make_float4(0.f, 0.f, 0.f, 0.f);
    float4 accZ = make_float4(0.f, 0.f, 0.f, 0.f);

    const int nr0 = 16 * strip;
    #pragma unroll
    for (int ks = 0; ks < 4; ks++) {
        const int k0 = ks * 16;
        unsigned a0, a1, a2, a3;
        const unsigned aaddr = Qbase +
            ((unsigned)((nr0 + arow_off) * P2 + k0 + acol_off)) * 2u;
        ldm_x4(a0, a1, a2, a3, aaddr);
        // Z fragment: B[k][n] = Kss[k] broadcast over n
        const unsigned zb0 = pack_h2(Kss[k0 + 2 * tig],     Kss[k0 + 2 * tig + 1]);
        const unsigned zb1 = pack_h2(Kss[k0 + 2 * tig + 8], Kss[k0 + 2 * tig + 9]);
        mma_fp16(accZ, a0, a1, a2, a3, zb0, zb1);
        #pragma unroll
        for (int j = 0; j < 4; j++) {
            const int m0 = 8 * (jt0 + j);
            unsigned b0, b1;
            const unsigned baddr = KVbase +
                ((unsigned)((k0 + brow_off) * P2 + m0)) * 2u;
            ldm_x2t(b0, b1, baddr);
            mma_fp16(acc[j], a0, a1, a2, a3, b0, b1);
        }
    }

    // per-lane normalizers from the Z-tile
    const float z0 = 1.0f / (accZ.x + 1e-6f);
    const float z1 = 1.0f / (accZ.z + 1e-6f);

    // epilogue: scale by Z, store
    const int row = nr0 + gid;
    float* op0 = Op + ((size_t)(b * Nq + n0 + row) * Hq + h) * Mq;
    float* op1 = op0 + (size_t)8 * Hq * Mq;
    #pragma unroll
    for (int j = 0; j < 4; j++) {
        const int m = 8 * (jt0 + j) + 2 * tig;
        *(float2*)(op0 + m) = make_float2(acc[j].x * z0, acc[j].y * z0);
        *(float2*)(op1 + m) = make_float2(acc[j].z * z1, acc[j].w * z1);
    }
}

extern "C" void kernel_launch(void* const* d_in, const int* in_sizes, int n_in,
                              void* d_out, int out_size) {
    const float* Q = (const float*)d_in[0];
    const float* K = (const float*)d_in[1];
    const float* V = (const float*)d_in[2];
    float* out = (float*)d_out;

    pass1_kernel<<<dim3(SEG, Hq, Bq), 256>>>(K, V);
    pass2_kernel<<<dim3(64, Hq, Bq), 256>>>(Q, out);
}